// round 3
// baseline (speedup 1.0000x reference)
#include <cuda_runtime.h>
#include <cstdint>

#define BH     64
#define SEQ    8192
#define DIM    64
#define NCHUNK 32
#define CHUNK  (SEQ / NCHUNK)   // 256
#define TS     16
#define NT     (CHUNK / TS)     // 16
#define P2R    64               // rows per CTA in phase 2

typedef unsigned long long u64;

// Scratch (allocation-free: __device__ globals)
__device__ float g_kv_part[BH * NCHUNK * DIM * DIM];  // 32 MB
__device__ float g_ks_part[BH * NCHUNK * DIM];
__device__ float g_kv[BH * DIM * DIM];
__device__ float g_ks[BH * DIM];

// ---- packed f32x2 helpers ---------------------------------------------------
__device__ __forceinline__ void unpack2(u64 v, float& lo, float& hi) {
    asm("mov.b64 {%0, %1}, %2;" : "=f"(lo), "=f"(hi) : "l"(v));
}
__device__ __forceinline__ void fma2(u64& d, u64 a, u64 b) {
    asm("fma.rn.f32x2 %0, %1, %2, %0;" : "+l"(d) : "l"(a), "l"(b));
}
__device__ __forceinline__ void add2(u64& d, u64 a) {
    asm("add.rn.f32x2 %0, %0, %1;" : "+l"(d) : "l"(a));
}

// swizzled column: insert 4-word gap every 32 words (kills tx bank wrap)
__device__ __forceinline__ int swz(int e) { return e + ((e >> 5) << 2); }

// ---------------------------------------------------------------------------
// Phase 1: partial kv = relu(K)^T @ V, ksum, per (head, chunk).
// 128 threads, 4d x 8e tiles. K staged relu'd AND duplicated; V bank-swizzled.
// Manual register double-buffering of tiles.
// ---------------------------------------------------------------------------
__global__ __launch_bounds__(128) void la_phase1(const float* __restrict__ K,
                                                 const float* __restrict__ V) {
    const int bh = blockIdx.x, chunk = blockIdx.y;
    const float* Kh = K + (size_t)bh * SEQ * DIM + (size_t)chunk * CHUNK * DIM;
    const float* Vh = V + (size_t)bh * SEQ * DIM + (size_t)chunk * CHUNK * DIM;

    __shared__ float Kd[2][TS][128];   // dup'd relu(K): [2d]=[2d+1]=relu(K[s][d])
    __shared__ float Vs[2][TS][68];    // swizzled V

    const int t  = threadIdx.x;
    const int tx = t & 7;              // e cols tx*8 .. +7
    const int ty = t >> 3;             // d rows ty*4 .. +3 (0..15)

    // staging mapping: 256 float4 per tile, 2 per thread (l=0,1)
    const int c4 = t & 15;
    const int r0 = t >> 4;             // + l*8
    const int vc_st = swz(c4 * 4);
    const int vcr   = swz(tx * 8);     // inner-loop V read col

    float4 kreg[2], vreg[2];

    u64 acc[4][4];
    u64 ksum2[4];
#pragma unroll
    for (int i = 0; i < 4; i++) {
        ksum2[i] = 0ull;
#pragma unroll
        for (int j = 0; j < 4; j++) acc[i][j] = 0ull;
    }

    auto ldg_tile = [&](int tile) {
#pragma unroll
        for (int l = 0; l < 2; l++) {
            const float* kb = Kh + ((size_t)(tile * TS + l * 8 + r0) * DIM + c4 * 4);
            const float* vb = Vh + ((size_t)(tile * TS + l * 8 + r0) * DIM + c4 * 4);
            kreg[l] = *(const float4*)kb;
            vreg[l] = *(const float4*)vb;
        }
    };
    auto sts_tile = [&](int buf) {
#pragma unroll
        for (int l = 0; l < 2; l++) {
            int row = l * 8 + r0;
            float4 k = kreg[l];
            k.x = fmaxf(k.x, 0.f); k.y = fmaxf(k.y, 0.f);
            k.z = fmaxf(k.z, 0.f); k.w = fmaxf(k.w, 0.f);
            *(float4*)&Kd[buf][row][c4 * 8]     = make_float4(k.x, k.x, k.y, k.y);
            *(float4*)&Kd[buf][row][c4 * 8 + 4] = make_float4(k.z, k.z, k.w, k.w);
            *(float4*)&Vs[buf][row][vc_st]      = vreg[l];
        }
    };

    // prologue
    ldg_tile(0);
    sts_tile(0);
    if (NT > 1) ldg_tile(1);
    __syncthreads();

    for (int tl = 0; tl < NT; tl++) {
        const int b = tl & 1;

#pragma unroll 8
        for (int s = 0; s < TS; s++) {
            ulonglong2 ka = *(const ulonglong2*)&Kd[b][s][ty * 8];      // dup d0,d1
            ulonglong2 kb = *(const ulonglong2*)&Kd[b][s][ty * 8 + 4];  // dup d2,d3
            ulonglong2 va = *(const ulonglong2*)&Vs[b][s][vcr];
            ulonglong2 vb = *(const ulonglong2*)&Vs[b][s][vcr + 4];

            add2(ksum2[0], ka.x); add2(ksum2[1], ka.y);
            add2(ksum2[2], kb.x); add2(ksum2[3], kb.y);

            fma2(acc[0][0], ka.x, va.x); fma2(acc[0][1], ka.x, va.y);
            fma2(acc[0][2], ka.x, vb.x); fma2(acc[0][3], ka.x, vb.y);
            fma2(acc[1][0], ka.y, va.x); fma2(acc[1][1], ka.y, va.y);
            fma2(acc[1][2], ka.y, vb.x); fma2(acc[1][3], ka.y, vb.y);
            fma2(acc[2][0], kb.x, va.x); fma2(acc[2][1], kb.x, va.y);
            fma2(acc[2][2], kb.x, vb.x); fma2(acc[2][3], kb.x, vb.y);
            fma2(acc[3][0], kb.y, va.x); fma2(acc[3][1], kb.y, va.y);
            fma2(acc[3][2], kb.y, vb.x); fma2(acc[3][3], kb.y, vb.y);
        }
        __syncthreads();
        if (tl + 1 < NT) {
            sts_tile(1 - b);            // regs hold tile tl+1
            if (tl + 2 < NT) ldg_tile(tl + 2);
            __syncthreads();
        }
    }

    float* kvp = g_kv_part + ((size_t)bh * NCHUNK + chunk) * DIM * DIM;
#pragma unroll
    for (int i = 0; i < 4; i++) {
        int d = ty * 4 + i;
        float o0, o1, o2, o3, o4, o5, o6, o7;
        unpack2(acc[i][0], o0, o1);
        unpack2(acc[i][1], o2, o3);
        unpack2(acc[i][2], o4, o5);
        unpack2(acc[i][3], o6, o7);
        *(float4*)&kvp[d * DIM + tx * 8]     = make_float4(o0, o1, o2, o3);
        *(float4*)&kvp[d * DIM + tx * 8 + 4] = make_float4(o4, o5, o6, o7);
    }
    if (tx == 0) {
#pragma unroll
        for (int i = 0; i < 4; i++) {
            float lo, hi;
            unpack2(ksum2[i], lo, hi);
            g_ks_part[((size_t)bh * NCHUNK + chunk) * DIM + ty * 4 + i] = lo;
        }
    }
}

// ---------------------------------------------------------------------------
// Reduce partials -> g_kv, g_ks
// ---------------------------------------------------------------------------
__global__ __launch_bounds__(256) void la_reduce() {
    const int bh  = blockIdx.x;
    const int tid = threadIdx.x;
    for (int idx = tid; idx < DIM * DIM; idx += 256) {
        float sum = 0.f;
#pragma unroll
        for (int c = 0; c < NCHUNK; c++)
            sum += g_kv_part[((size_t)bh * NCHUNK + c) * DIM * DIM + idx];
        g_kv[(size_t)bh * DIM * DIM + idx] = sum;
    }
    if (tid < DIM) {
        float s = 0.f;
#pragma unroll
        for (int c = 0; c < NCHUNK; c++)
            s += g_ks_part[((size_t)bh * NCHUNK + c) * DIM + tid];
        g_ks[bh * DIM + tid] = s;
    }
}

// ---------------------------------------------------------------------------
// Phase 2: out = relu(Q) @ kv / max(relu(Q)·ksum, 1e-6).
// 128 threads, 64 rows x 64 cols, 4x8 thread tiles. Q staged relu'd+dup'd in
// 4 column passes; kv bank-swizzled in smem; ksum dup'd.
// ---------------------------------------------------------------------------
__global__ __launch_bounds__(128) void la_phase2(const float* __restrict__ Q,
                                                 float* __restrict__ O) {
    const int bh = blockIdx.x;
    const int rb = blockIdx.y;
    const float* Qh = Q + (size_t)bh * SEQ * DIM + (size_t)rb * P2R * DIM;
    float* Oh       = O + (size_t)bh * SEQ * DIM + (size_t)rb * P2R * DIM;

    __shared__ float kvs[DIM][68];     // swizzled kv
    __shared__ float qs[P2R][36];      // dup'd relu(Q), 16 d-cols per pass
    __shared__ float kssd[2 * DIM + 2];

    const int tid = threadIdx.x;
    const int tx  = tid & 7;           // e cols tx*8 .. +7
    const int ty  = tid >> 3;          // rows ty*4 .. +3 (0..15)
    const int kc  = swz(tx * 8);

    // stage kv (swizzled): 1024 float4 / 128 thr = 8 each
    const float4* kvg = (const float4*)(g_kv + (size_t)bh * DIM * DIM);
#pragma unroll
    for (int l = 0; l < 8; l++) {
        int idx = l * 128 + tid;
        int row = idx >> 4;
        int c4  = idx & 15;
        *(float4*)&kvs[row][swz(c4 * 4)] = kvg[idx];
    }
    if (tid < DIM) {
        float s = g_ks[bh * DIM + tid];
        kssd[2 * tid] = s; kssd[2 * tid + 1] = s;
    }

    u64 acc[4][4];
    u64 nrm2[4];
#pragma unroll
    for (int i = 0; i < 4; i++) {
        nrm2[i] = 0ull;
#pragma unroll
        for (int j = 0; j < 4; j++) acc[i][j] = 0ull;
    }

    for (int pass = 0; pass < 4; pass++) {
        __syncthreads();
        // stage relu(Q) dup'd, cols [pass*16, +16): 256 float4 / 128 thr = 2
#pragma unroll
        for (int l = 0; l < 2; l++) {
            int idx = l * 128 + tid;
            int row = idx >> 2;
            int cg  = idx & 3;
            float4 q = *(const float4*)(Qh + (size_t)row * DIM + pass * 16 + cg * 4);
            q.x = fmaxf(q.x, 0.f); q.y = fmaxf(q.y, 0.f);
            q.z = fmaxf(q.z, 0.f); q.w = fmaxf(q.w, 0.f);
            *(float4*)&qs[row][cg * 8]     = make_float4(q.x, q.x, q.y, q.y);
            *(float4*)&qs[row][cg * 8 + 4] = make_float4(q.z, q.z, q.w, q.w);
        }
        __syncthreads();

#pragma unroll
        for (int p = 0; p < 8; p++) {
            const int d0 = pass * 16 + 2 * p;
            u64 ks0 = *(const u64*)&kssd[2 * d0];
            u64 ks1 = *(const u64*)&kssd[2 * d0 + 2];
            ulonglong2 a_lo = *(const ulonglong2*)&kvs[d0][kc];
            ulonglong2 a_hi = *(const ulonglong2*)&kvs[d0][kc + 4];
            ulonglong2 b_lo = *(const ulonglong2*)&kvs[d0 + 1][kc];
            ulonglong2 b_hi = *(const ulonglong2*)&kvs[d0 + 1][kc + 4];
#pragma unroll
            for (int i = 0; i < 4; i++) {
                ulonglong2 qd = *(const ulonglong2*)&qs[ty * 4 + i][p * 4];
                // qd.x = dup(q[d0]), qd.y = dup(q[d0+1])
                fma2(nrm2[i], qd.x, ks0);
                fma2(nrm2[i], qd.y, ks1);
                fma2(acc[i][0], qd.x, a_lo.x); fma2(acc[i][1], qd.x, a_lo.y);
                fma2(acc[i][2], qd.x, a_hi.x); fma2(acc[i][3], qd.x, a_hi.y);
                fma2(acc[i][0], qd.y, b_lo.x); fma2(acc[i][1], qd.y, b_lo.y);
                fma2(acc[i][2], qd.y, b_hi.x); fma2(acc[i][3], qd.y, b_hi.y);
            }
        }
    }

#pragma unroll
    for (int i = 0; i < 4; i++) {
        float nl, nh;
        unpack2(nrm2[i], nl, nh);      // both halves equal; use lo
        float inv = 1.f / fmaxf(nl, 1e-6f);
        float o0, o1, o2, o3, o4, o5, o6, o7;
        unpack2(acc[i][0], o0, o1);
        unpack2(acc[i][1], o2, o3);
        unpack2(acc[i][2], o4, o5);
        unpack2(acc[i][3], o6, o7);
        int row = ty * 4 + i;
        *(float4*)&Oh[(size_t)row * DIM + tx * 8] =
            make_float4(o0 * inv, o1 * inv, o2 * inv, o3 * inv);
        *(float4*)&Oh[(size_t)row * DIM + tx * 8 + 4] =
            make_float4(o4 * inv, o5 * inv, o6 * inv, o7 * inv);
    }
}

// ---------------------------------------------------------------------------
extern "C" void kernel_launch(void* const* d_in, const int* in_sizes, int n_in,
                              void* d_out, int out_size) {
    const float* q = (const float*)d_in[0];
    const float* k = (const float*)d_in[1];
    const float* v = (const float*)d_in[2];
    float* o = (float*)d_out;

    la_phase1<<<dim3(BH, NCHUNK), 128>>>(k, v);
    la_reduce<<<BH, 256>>>();
    la_phase2<<<dim3(BH, SEQ / P2R), 128>>>(q, o);
}

// round 5
// speedup vs baseline: 1.2677x; 1.2677x over previous
#include <cuda_runtime.h>
#include <cuda_bf16.h>
#include <cstdint>

#define BH     64
#define SEQ    8192
#define DIM    64
#define NCHUNK 32
#define CHUNK  (SEQ / NCHUNK)   // 256
#define TS     16
#define NT     (CHUNK / TS)     // 16

typedef unsigned long long u64;

// Scratch (allocation-free: __device__ globals)
__device__ float g_kv_part[BH * NCHUNK * DIM * DIM];  // 32 MB
__device__ float g_ks_part[BH * NCHUNK * DIM];
__device__ float g_kvT[BH * 72 * DIM];                // [e(64)+ksum(1)+pad(7)][d(64)]

// ---- packed f32x2 helpers ---------------------------------------------------
__device__ __forceinline__ u64 pack2(float lo, float hi) {
    u64 r;
    asm("mov.b64 %0, {%1, %2};" : "=l"(r) : "f"(lo), "f"(hi));
    return r;
}
__device__ __forceinline__ void unpack2(u64 v, float& lo, float& hi) {
    asm("mov.b64 {%0, %1}, %2;" : "=f"(lo), "=f"(hi) : "l"(v));
}
__device__ __forceinline__ void fma2(u64& d, u64 a, u64 b) {
    asm("fma.rn.f32x2 %0, %1, %2, %0;" : "+l"(d) : "l"(a), "l"(b));
}
// ---- cp.async helpers --------------------------------------------------------
__device__ __forceinline__ void cp16(void* s, const void* g) {
    uint32_t sa = (uint32_t)__cvta_generic_to_shared(s);
    asm volatile("cp.async.cg.shared.global [%0], [%1], 16;"
                 :: "r"(sa), "l"(g) : "memory");
}
#define CP_COMMIT() asm volatile("cp.async.commit_group;" ::: "memory")
#define CP_WAIT1()  asm volatile("cp.async.wait_group 1;" ::: "memory")

// ---------------------------------------------------------------------------
// Phase 1 (unchanged, measured best): partial kv = relu(K)^T @ V, ksum.
// ---------------------------------------------------------------------------
__global__ __launch_bounds__(64) void la_phase1(const float* __restrict__ K,
                                                const float* __restrict__ V) {
    const int bh = blockIdx.x, chunk = blockIdx.y;
    const float* Kh = K + (size_t)bh * SEQ * DIM + (size_t)chunk * CHUNK * DIM;
    const float* Vh = V + (size_t)bh * SEQ * DIM + (size_t)chunk * CHUNK * DIM;

    __shared__ float Ks[2][TS][DIM];
    __shared__ float Vs[2][TS][DIM];

    const int t  = threadIdx.x;
    const int tx = t & 7;
    const int ty = t >> 3;

    int crow[4], ccol[4];
#pragma unroll
    for (int l = 0; l < 4; l++) {
        int idx = l * 64 + t;
        crow[l] = idx >> 4;
        ccol[l] = (idx & 15) * 4;
    }

    u64 acc[8][4];
    float ksum[8];
#pragma unroll
    for (int i = 0; i < 8; i++) {
        ksum[i] = 0.f;
#pragma unroll
        for (int j = 0; j < 4; j++) acc[i][j] = 0ull;
    }

#pragma unroll
    for (int p = 0; p < 2; p++) {
#pragma unroll
        for (int l = 0; l < 4; l++) {
            cp16(&Ks[p][crow[l]][ccol[l]],
                 Kh + (size_t)(p * TS + crow[l]) * DIM + ccol[l]);
            cp16(&Vs[p][crow[l]][ccol[l]],
                 Vh + (size_t)(p * TS + crow[l]) * DIM + ccol[l]);
        }
        CP_COMMIT();
    }

    for (int tl = 0; tl < NT; tl++) {
        CP_WAIT1();
        __syncthreads();
        const int b = tl & 1;

#pragma unroll 8
        for (int s = 0; s < TS; s++) {
            float4 ka = *(const float4*)&Ks[b][s][ty * 8];
            float4 kb = *(const float4*)&Ks[b][s][ty * 8 + 4];
            ulonglong2 va = *(const ulonglong2*)&Vs[b][s][tx * 8];
            ulonglong2 vb = *(const ulonglong2*)&Vs[b][s][tx * 8 + 4];
            float kf[8] = {ka.x, ka.y, ka.z, ka.w, kb.x, kb.y, kb.z, kb.w};
#pragma unroll
            for (int i = 0; i < 8; i++) {
                float km = fmaxf(kf[i], 0.f);
                ksum[i] += km;
                u64 k2 = pack2(km, km);
                fma2(acc[i][0], k2, va.x);
                fma2(acc[i][1], k2, va.y);
                fma2(acc[i][2], k2, vb.x);
                fma2(acc[i][3], k2, vb.y);
            }
        }
        __syncthreads();

        if (tl + 2 < NT) {
#pragma unroll
            for (int l = 0; l < 4; l++) {
                cp16(&Ks[b][crow[l]][ccol[l]],
                     Kh + (size_t)((tl + 2) * TS + crow[l]) * DIM + ccol[l]);
                cp16(&Vs[b][crow[l]][ccol[l]],
                     Vh + (size_t)((tl + 2) * TS + crow[l]) * DIM + ccol[l]);
            }
        }
        CP_COMMIT();
    }

    float* kvp = g_kv_part + ((size_t)bh * NCHUNK + chunk) * DIM * DIM;
#pragma unroll
    for (int i = 0; i < 8; i++) {
        int d = ty * 8 + i;
        float o0, o1, o2, o3, o4, o5, o6, o7;
        unpack2(acc[i][0], o0, o1);
        unpack2(acc[i][1], o2, o3);
        unpack2(acc[i][2], o4, o5);
        unpack2(acc[i][3], o6, o7);
        *(float4*)&kvp[d * DIM + tx * 8]     = make_float4(o0, o1, o2, o3);
        *(float4*)&kvp[d * DIM + tx * 8 + 4] = make_float4(o4, o5, o6, o7);
    }
    if (tx == 0) {
#pragma unroll
        for (int i = 0; i < 8; i++)
            g_ks_part[((size_t)bh * NCHUNK + chunk) * DIM + ty * 8 + i] = ksum[i];
    }
}

// ---------------------------------------------------------------------------
// Reduce partials -> g_kvT[bh][72][64]: rows 0-63 = kv^T, row 64 = ksum,
// rows 65-71 = 0 (N padding so phase2 can use 9 n-tiles of 8).
// ---------------------------------------------------------------------------
__global__ __launch_bounds__(256) void la_reduce() {
    const int bh  = blockIdx.x;
    const int tid = threadIdx.x;
    float* outT = g_kvT + (size_t)bh * 72 * DIM;
    for (int idx = tid; idx < DIM * DIM; idx += 256) {
        int d = idx >> 6, e = idx & 63;
        float sum = 0.f;
#pragma unroll
        for (int c = 0; c < NCHUNK; c++)
            sum += g_kv_part[((size_t)bh * NCHUNK + c) * DIM * DIM + idx];
        outT[e * DIM + d] = sum;
    }
    if (tid < DIM) {
        float s = 0.f;
#pragma unroll
        for (int c = 0; c < NCHUNK; c++)
            s += g_ks_part[((size_t)bh * NCHUNK + c) * DIM + tid];
        outT[64 * DIM + tid] = s;
    }
    for (int i = tid; i < 7 * DIM; i += 256)
        outT[65 * DIM + i] = 0.f;
}

// ===========================================================================
// Phase 2 on mma.sync bf16 (3-term split folded into K):
//   A'[128 x 192] = [relu(Q)_hi | relu(Q)_hi | relu(Q)_lo]
//   B'[ 72 x 192] = [kvT_hi     | kvT_lo     | kvT_hi    ]
//   D[128 x 72] = A' @ B'^T ; col 64 = normalizer.
// 256 threads: warp w owns m-tile rows w*16..w*16+15. 9 n-tiles, 12 k-steps.
// smem rows padded to 200 bf16 (400 B) -> conflict-free ldmatrix.
// ===========================================================================
#define KPAD 200
#define A_BYTES (128 * KPAD * 2)   // 51200
#define B_BYTES (72 * KPAD * 2)    // 28800
#define P2_SMEM (A_BYTES + B_BYTES)

__device__ __forceinline__ uint32_t pack_bf2(__nv_bfloat16 lo, __nv_bfloat16 hi) {
    __nv_bfloat162 t = __halves2bfloat162(lo, hi);
    return *(uint32_t*)&t;
}

__global__ __launch_bounds__(256) void la_phase2(const float* __restrict__ Q,
                                                 float* __restrict__ O) {
    extern __shared__ char sm[];
    __nv_bfloat16* As = (__nv_bfloat16*)sm;
    __nv_bfloat16* Bs = (__nv_bfloat16*)(sm + A_BYTES);

    const int bh = blockIdx.x;
    const int rb = blockIdx.y;
    const float* Qh = Q + (size_t)bh * SEQ * DIM + (size_t)rb * 128 * DIM;

    const int tid  = threadIdx.x;
    const int lane = tid & 31;
    const int wid  = tid >> 5;

    // ---- stage A': 2048 float4 / 256 thr = 8 each ----
#pragma unroll
    for (int l = 0; l < 8; l++) {
        int idx = l * 256 + tid;
        int m = idx >> 4;
        int k = (idx & 15) * 4;
        float4 q = *(const float4*)(Qh + (size_t)m * DIM + k);
        q.x = fmaxf(q.x, 0.f); q.y = fmaxf(q.y, 0.f);
        q.z = fmaxf(q.z, 0.f); q.w = fmaxf(q.w, 0.f);
        __nv_bfloat16 hx = __float2bfloat16_rn(q.x), hy = __float2bfloat16_rn(q.y);
        __nv_bfloat16 hz = __float2bfloat16_rn(q.z), hw = __float2bfloat16_rn(q.w);
        __nv_bfloat16 lx = __float2bfloat16_rn(q.x - __bfloat162float(hx));
        __nv_bfloat16 ly = __float2bfloat16_rn(q.y - __bfloat162float(hy));
        __nv_bfloat16 lz = __float2bfloat16_rn(q.z - __bfloat162float(hz));
        __nv_bfloat16 lw = __float2bfloat16_rn(q.w - __bfloat162float(hw));
        uint2 hv = make_uint2(pack_bf2(hx, hy), pack_bf2(hz, hw));
        uint2 lv = make_uint2(pack_bf2(lx, ly), pack_bf2(lz, lw));
        __nv_bfloat16* row = As + (size_t)m * KPAD;
        *(uint2*)(row + k)       = hv;   // section 0: hi
        *(uint2*)(row + 64 + k)  = hv;   // section 1: hi
        *(uint2*)(row + 128 + k) = lv;   // section 2: lo
    }
    // ---- stage B': 1152 float4 / 256 thr ----
    const float* Bg = g_kvT + (size_t)bh * 72 * DIM;
    for (int idx = tid; idx < 72 * 16; idx += 256) {
        int n = idx >> 4;
        int k = (idx & 15) * 4;
        float4 b = *(const float4*)(Bg + (size_t)n * DIM + k);
        __nv_bfloat16 hx = __float2bfloat16_rn(b.x), hy = __float2bfloat16_rn(b.y);
        __nv_bfloat16 hz = __float2bfloat16_rn(b.z), hw = __float2bfloat16_rn(b.w);
        __nv_bfloat16 lx = __float2bfloat16_rn(b.x - __bfloat162float(hx));
        __nv_bfloat16 ly = __float2bfloat16_rn(b.y - __bfloat162float(hy));
        __nv_bfloat16 lz = __float2bfloat16_rn(b.z - __bfloat162float(hz));
        __nv_bfloat16 lw = __float2bfloat16_rn(b.w - __bfloat162float(hw));
        uint2 hv = make_uint2(pack_bf2(hx, hy), pack_bf2(hz, hw));
        uint2 lv = make_uint2(pack_bf2(lx, ly), pack_bf2(lz, lw));
        __nv_bfloat16* row = Bs + (size_t)n * KPAD;
        *(uint2*)(row + k)       = hv;   // section 0: hi
        *(uint2*)(row + 64 + k)  = lv;   // section 1: lo
        *(uint2*)(row + 128 + k) = hv;   // section 2: hi
    }
    __syncthreads();

    // ---- mainloop ----
    const int m0 = wid * 16;
    uint32_t Abase = (uint32_t)__cvta_generic_to_shared(As);
    uint32_t Bbase = (uint32_t)__cvta_generic_to_shared(Bs);
    // ldmatrix.x4 A: lanes 0-7 rows m0..m0+7 @k0, 8-15 rows +8 @k0,
    //                16-23 rows m0..m0+7 @k0+8, 24-31 rows +8 @k0+8
    uint32_t aAddr = Abase + (uint32_t)(m0 + (lane & 15)) * (KPAD * 2)
                   + (uint32_t)(lane >> 4) * 16;
    // ldmatrix.x2 B: lanes 0-7 rows n0..n0+7 @k0, 8-15 rows n0..n0+7 @k0+8
    uint32_t bAddr = Bbase + (uint32_t)(lane & 7) * (KPAD * 2)
                   + (uint32_t)((lane >> 3) & 1) * 16;

    float acc[9][4];
#pragma unroll
    for (int j = 0; j < 9; j++)
#pragma unroll
        for (int r = 0; r < 4; r++) acc[j][r] = 0.f;

#pragma unroll
    for (int ks = 0; ks < 12; ks++) {
        uint32_t a0, a1, a2, a3;
        asm volatile("ldmatrix.sync.aligned.m8n8.x4.shared.b16 {%0,%1,%2,%3}, [%4];"
                     : "=r"(a0), "=r"(a1), "=r"(a2), "=r"(a3)
                     : "r"(aAddr + ks * 32));
#pragma unroll
        for (int j = 0; j < 9; j++) {
            uint32_t b0, b1;
            asm volatile("ldmatrix.sync.aligned.m8n8.x2.shared.b16 {%0,%1}, [%2];"
                         : "=r"(b0), "=r"(b1)
                         : "r"(bAddr + j * (8 * KPAD * 2) + ks * 32));
            asm volatile(
                "mma.sync.aligned.m16n8k16.row.col.f32.bf16.bf16.f32 "
                "{%0,%1,%2,%3}, {%4,%5,%6,%7}, {%8,%9}, {%0,%1,%2,%3};"
                : "+f"(acc[j][0]), "+f"(acc[j][1]), "+f"(acc[j][2]), "+f"(acc[j][3])
                : "r"(a0), "r"(a1), "r"(a2), "r"(a3), "r"(b0), "r"(b1));
        }
    }

    // ---- epilogue: normalizer = col 64 (n-tile 8, local col 0, held by tg==0)
    const int g  = lane >> 2;
    const int tg = lane & 3;
    float nlo = __shfl_sync(0xffffffffu, acc[8][0], lane & ~3);
    float nhi = __shfl_sync(0xffffffffu, acc[8][2], lane & ~3);
    float ilo = 1.f / fmaxf(nlo, 1e-6f);
    float ihi = 1.f / fmaxf(nhi, 1e-6f);

    float* O0 = O + ((size_t)bh * SEQ + (size_t)rb * 128 + m0 + g) * DIM + 2 * tg;
    float* O1 = O0 + 8 * DIM;
#pragma unroll
    for (int j = 0; j < 8; j++) {
        *(float2*)(O0 + j * 8) = make_float2(acc[j][0] * ilo, acc[j][1] * ilo);
        *(float2*)(O1 + j * 8) = make_float2(acc[j][2] * ihi, acc[j][3] * ihi);
    }
}

// ---------------------------------------------------------------------------
extern "C" void kernel_launch(void* const* d_in, const int* in_sizes, int n_in,
                              void* d_out, int out_size) {
    const float* q = (const float*)d_in[0];
    const float* k = (const float*)d_in[1];
    const float* v = (const float*)d_in[2];
    float* o = (float*)d_out;

    static bool configured = false;
    if (!configured) {
        cudaFuncSetAttribute(la_phase2, cudaFuncAttributeMaxDynamicSharedMemorySize,
                             P2_SMEM);
        configured = true;
    }

    la_phase1<<<dim3(BH, NCHUNK), 64>>>(k, v);
    la_reduce<<<BH, 256>>>();
    la_phase2<<<dim3(BH, SEQ / 128), 256, P2_SMEM>>>(q, o);
}